// round 10
// baseline (speedup 1.0000x reference)
#include <cuda_runtime.h>
#include <cuda_fp16.h>

#define NB 4
#define NS 2048
#define ND 1024
#define NH 16
#define HD 64
#define NEGV (-10000.0f)
#define SCALE 0.125f
#define SROW 2052   // fp32 score row stride; %32==4 conflict-free, %4==0 for float4

// ---------------- scratch (static device arrays; no runtime allocation) ------------
__device__ float g_qh[NB * NH * NS * HD];
__device__ float g_kh[NB * NH * NS * HD];
__device__ float g_vh[NB * NH * NS * HD];
__device__ float g_ao[NB * NS * ND];

// ---------------- helpers ----------------------------------------------------------
__device__ __forceinline__ unsigned f2tf(float x) {
    unsigned u; asm("cvt.rna.tf32.f32 %0, %1;" : "=r"(u) : "f"(x)); return u;
}
__device__ __forceinline__ float f2tff(float x) { return __uint_as_float(f2tf(x)); }

__device__ __forceinline__ unsigned packh2(float x, float y) {
    __half2 h = __floats2half2_rn(x, y);
    return *reinterpret_cast<unsigned*>(&h);
}

__device__ __forceinline__ void mma_tf32(float c[4], const unsigned a[4], const unsigned b[2]) {
    asm volatile(
        "mma.sync.aligned.m16n8k8.row.col.f32.tf32.tf32.f32 "
        "{%0,%1,%2,%3}, {%4,%5,%6,%7}, {%8,%9}, {%0,%1,%2,%3};"
        : "+f"(c[0]), "+f"(c[1]), "+f"(c[2]), "+f"(c[3])
        : "r"(a[0]), "r"(a[1]), "r"(a[2]), "r"(a[3]), "r"(b[0]), "r"(b[1]));
}

__device__ __forceinline__ void mma_f16(float c[4], const unsigned a[4], const unsigned b[2]) {
    asm volatile(
        "mma.sync.aligned.m16n8k16.row.col.f32.f16.f16.f32 "
        "{%0,%1,%2,%3}, {%4,%5,%6,%7}, {%8,%9}, {%0,%1,%2,%3};"
        : "+f"(c[0]), "+f"(c[1]), "+f"(c[2]), "+f"(c[3])
        : "r"(a[0]), "r"(a[1]), "r"(a[2]), "r"(a[3]), "r"(b[0]), "r"(b[1]));
}

// ---------------- QKV projection: Y = X @ W^T + b (fp16 m16n8k16) ------------------
// CTA 128x128, BK=16, 256 thr = 8 warps, warp tile 64x32; double-buffered fp16 smem.
// As/Bs: m-/n-major, 24 halfs (12 words) per row -> bank-conflict-free frags.
__global__ __launch_bounds__(256) void proj_kernel(
    const float* __restrict__ X, const float* __restrict__ W,
    const float* __restrict__ bias, int which)
{
    __shared__ __align__(16) unsigned Asw[2][128 * 12];
    __shared__ __align__(16) unsigned Bsw[2][128 * 12];
    float* out = (which == 0) ? g_qh : (which == 1) ? g_kh : g_vh;

    const int t = threadIdx.x;
    const int lane = t & 31, w = t >> 5;
    const int g = lane >> 2, tg = lane & 3;
    const int m0 = blockIdx.x * 128;
    const int n0 = blockIdx.y * 128;
    const int wm = (w & 1) * 64;
    const int wn = (w >> 1) * 32;

    float acc[4][4][4];
#pragma unroll
    for (int mt = 0; mt < 4; mt++)
#pragma unroll
        for (int nt = 0; nt < 4; nt++)
#pragma unroll
            for (int r = 0; r < 4; r++) acc[mt][nt][r] = 0.0f;

    int stage = 0;
    for (int k0 = 0; k0 < ND; k0 += 16, stage ^= 1) {
#pragma unroll
        for (int r = 0; r < 2; r++) {
            const int idx = t + 256 * r;
            const int row = idx >> 2, qc = (idx & 3) * 4;   // qc: 0,4,8,12 (halfs)
            float4 av = *(const float4*)(X + (size_t)(m0 + row) * ND + k0 + qc);
            *(uint2*)&Asw[stage][row * 12 + qc / 2] =
                make_uint2(packh2(av.x, av.y), packh2(av.z, av.w));
            float4 bv = *(const float4*)(W + (size_t)(n0 + row) * ND + k0 + qc);
            *(uint2*)&Bsw[stage][row * 12 + qc / 2] =
                make_uint2(packh2(bv.x, bv.y), packh2(bv.z, bv.w));
        }
        __syncthreads();   // single barrier/iter (skewed double buffer)
        unsigned a[4][4], b[4][2];
#pragma unroll
        for (int mt = 0; mt < 4; mt++) {
            const int m = wm + mt * 16 + g;
            a[mt][0] = Asw[stage][m * 12 + tg];
            a[mt][1] = Asw[stage][(m + 8) * 12 + tg];
            a[mt][2] = Asw[stage][m * 12 + tg + 4];
            a[mt][3] = Asw[stage][(m + 8) * 12 + tg + 4];
        }
#pragma unroll
        for (int nt = 0; nt < 4; nt++) {
            const int n = wn + nt * 8 + g;
            b[nt][0] = Bsw[stage][n * 12 + tg];
            b[nt][1] = Bsw[stage][n * 12 + tg + 4];
        }
#pragma unroll
        for (int mt = 0; mt < 4; mt++)
#pragma unroll
            for (int nt = 0; nt < 4; nt++)
                mma_f16(acc[mt][nt], a[mt], b[nt]);
    }

#pragma unroll
    for (int mt = 0; mt < 4; mt++) {
#pragma unroll
        for (int rr = 0; rr < 2; rr++) {
            const int row = m0 + wm + mt * 16 + g + rr * 8;
            const int b_ = row / NS, s = row % NS;
#pragma unroll
            for (int nt = 0; nt < 4; nt++) {
                const int col = n0 + wn + nt * 8 + tg * 2;
                const int h = col >> 6, d = col & 63;
                float2 val;
                val.x = acc[mt][nt][rr * 2 + 0] + bias[col];
                val.y = acc[mt][nt][rr * 2 + 1] + bias[col + 1];
                *(float2*)&out[(((size_t)b_ * NH + h) * NS + s) * HD + d] = val;
            }
        }
    }
}

// ---------------- attention: one block (512 thr, 16 warps) per (b,h,16-query tile) --
// smem: scores fp32[16][2052] | R: {fp16 K 2x[256][72]  OR  fp32 V 2x[128][68] / part}
//       | Qs fp16[16][72] | inv_s[16]
#define SCORES_B (16 * SROW * 4)            // 131328
#define R_B      (2 * 256 * 36 * 4)         // 73728 bytes (>= 2*128*68*4 = 69632)
#define QS_OFF   (SCORES_B + R_B)           // 205056
#define INV_OFF  (QS_OFF + 16 * 36 * 4)     // 207360 (Qs: 36 words/row, 16 rows)
#define SMEM_B   (INV_OFF + 64)             // 207424

__global__ __launch_bounds__(512) void attn_kernel(const int* __restrict__ mask,
                                                   float* __restrict__ attn_out)
{
    extern __shared__ __align__(16) char smc[];
    float*    scores = (float*)smc;
    unsigned* kw     = (unsigned*)(smc + SCORES_B);   // fp16 K words, 36 words/key
    float*    vb0    = (float*)(smc + SCORES_B);      // phase-4 fp32 V buffers
    float*    vb1    = vb0 + 128 * 68;
    float*    part   = vb0;                           // phase-4 partials alias
    unsigned* qw     = (unsigned*)(smc + QS_OFF);     // fp16 Q words, 36 words/row
    float*    inv_s  = (float*)(smc + INV_OFF);

    const int t    = threadIdx.x;
    const int lane = t & 31, w = t >> 5;              // w: 0..15
    const int g = lane >> 2, tg = lane & 3;
    const int bid = blockIdx.x;
    const int qt = bid & 127;
    const int h  = (bid >> 7) & 15;
    const int b  = bid >> 11;
    const int q0 = qt * 16;

    const size_t bh = (size_t)(b * NH + h);
    const float* qbase = g_qh + bh * NS * HD;
    const float* kbase = g_kh + bh * NS * HD;
    const float* vbase = g_vh + bh * NS * HD;

    // ---- stage Q (scaled, fp16) into Qs[16][72 halfs] (stride 36 words >= 32 needed) ----
    if (t < 256) {
        const int row = t >> 4, kd4 = (t & 15);
        float4 qv = *(const float4*)(qbase + (size_t)(q0 + row) * HD + kd4 * 4);
        *(uint2*)&qw[row * 36 + kd4 * 2] =
            make_uint2(packh2(qv.x * SCALE, qv.y * SCALE), packh2(qv.z * SCALE, qv.w * SCALE));
    }
    __syncthreads();

    // preload Q fragments for the 4 k16-steps
    unsigned aq[4][4];
#pragma unroll
    for (int ks = 0; ks < 4; ks++) {
        aq[ks][0] = qw[g * 36 + ks * 8 + tg];
        aq[ks][1] = qw[(g + 8) * 36 + ks * 8 + tg];
        aq[ks][2] = qw[g * 36 + ks * 8 + tg + 4];
        aq[ks][3] = qw[(g + 8) * 36 + ks * 8 + tg + 4];
    }

    // ---- phase 1: scores = (q*scale) @ K^T, fp16 m16n8k16, 256-key chunks ----
    for (int jc = 0; jc < 8; jc++) {
        const int j0 = jc * 256;
        unsigned* kb = kw + (jc & 1) * 256 * 36;
#pragma unroll
        for (int r = 0; r < 8; r++) {
            const int idx = t + 512 * r;
            const int key = idx >> 4, kd4 = (idx & 15);
            float4 kv = *(const float4*)(kbase + (size_t)(j0 + key) * HD + kd4 * 4);
            unsigned w0 = packh2(kv.x, kv.y), w1 = packh2(kv.z, kv.w);
            if (key & 1) { unsigned tmp = w0; w0 = w1; w1 = tmp; }  // low-bit swizzle
            *(uint2*)&kb[key * 36 + kd4 * 2] = make_uint2(w0, w1);
        }
        __syncthreads();
#pragma unroll
        for (int cg = 0; cg < 2; cg++) {
            const int lkey = w * 16 + cg * 8;
            const int key = lkey + g;
            const int p = g & 1;                       // parity of key (lkey even)
            const unsigned* krow = kb + key * 36;
            float cA[4] = {0.f, 0.f, 0.f, 0.f}, cB[4] = {0.f, 0.f, 0.f, 0.f};
#pragma unroll
            for (int ks = 0; ks < 4; ks++) {
                unsigned bb[2];
                bb[0] = krow[(ks * 8 + tg) ^ p];
                bb[1] = krow[(ks * 8 + tg + 4) ^ p];
                mma_f16((ks & 1) ? cB : cA, aq[ks], bb);
            }
            const int col = j0 + lkey + tg * 2;
            *(float2*)&scores[g * SROW + col]       = make_float2(cA[0] + cB[0], cA[1] + cB[1]);
            *(float2*)&scores[(g + 8) * SROW + col] = make_float2(cA[2] + cB[2], cA[3] + cB[3]);
        }
    }
    __syncthreads();

    // ---- phase 2: masks + softmax; warp w owns row w; vectorized ----
    {
        const int i = w;
        const int qrow = q0 + i;
        const int* mrow = mask + ((size_t)b * NS + qrow) * NS;
        float mx = -3.0e38f;
        for (int k4 = lane * 4; k4 < NS; k4 += 128) {
            int4 m4 = *(const int4*)(mrow + k4);
            float4 s4 = *(float4*)(scores + i * SROW + k4);
            s4.x += (1.0f - (float)m4.x) * NEGV + ((k4 + 0 > qrow) ? NEGV : 0.0f);
            s4.y += (1.0f - (float)m4.y) * NEGV + ((k4 + 1 > qrow) ? NEGV : 0.0f);
            s4.z += (1.0f - (float)m4.z) * NEGV + ((k4 + 2 > qrow) ? NEGV : 0.0f);
            s4.w += (1.0f - (float)m4.w) * NEGV + ((k4 + 3 > qrow) ? NEGV : 0.0f);
            *(float4*)(scores + i * SROW + k4) = s4;
            mx = fmaxf(mx, fmaxf(fmaxf(s4.x, s4.y), fmaxf(s4.z, s4.w)));
        }
#pragma unroll
        for (int o = 16; o > 0; o >>= 1) mx = fmaxf(mx, __shfl_xor_sync(0xffffffffu, mx, o));
        float sum = 0.0f;
        for (int k4 = lane * 4; k4 < NS; k4 += 128) {
            float4 s4 = *(float4*)(scores + i * SROW + k4);
            s4.x = __expf(s4.x - mx); s4.y = __expf(s4.y - mx);
            s4.z = __expf(s4.z - mx); s4.w = __expf(s4.w - mx);
            *(float4*)(scores + i * SROW + k4) = s4;
            sum += (s4.x + s4.y) + (s4.z + s4.w);
        }
#pragma unroll
        for (int o = 16; o > 0; o >>= 1) sum += __shfl_xor_sync(0xffffffffu, sum, o);
        if (lane == 0) inv_s[i] = 1.0f / sum;
    }
    __syncthreads();

    // ---- phase 3: write normalized attention probabilities (float4) ----
    if (attn_out) {
        for (int idx = t; idx < 16 * 512; idx += 512) {
            const int i = idx >> 9, j = (idx & 511) * 4;
            float4 p = *(float4*)(scores + i * SROW + j);
            const float iv = inv_s[i];
            p.x *= iv; p.y *= iv; p.z *= iv; p.w *= iv;
            *(float4*)&attn_out[(bh * NS + q0 + i) * (size_t)NS + j] = p;
        }
    }

    // ---- phase 4: out = P @ V (tf32); warp w -> 8 keys, full 64-wide N ----
    {
        float pc[8][4];
#pragma unroll
        for (int nt = 0; nt < 8; nt++)
#pragma unroll
            for (int r = 0; r < 4; r++) pc[nt][r] = 0.0f;

        for (int jc = 0; jc < 16; jc++) {
            const int j0 = jc * 128;
            float* bufc = (jc & 1) ? vb1 : vb0;
#pragma unroll
            for (int r = 0; r < 4; r++) {
                const int idx = t + 512 * r;
                const int key = idx >> 4, kd = (idx & 15) * 4;
                float4 vv = *(const float4*)(vbase + (size_t)(j0 + key) * HD + kd);
                float4 s4;
                s4.x = f2tff(vv.x); s4.y = f2tff(vv.y);
                s4.z = f2tff(vv.z); s4.w = f2tff(vv.w);
                *(float4*)(bufc + key * 68 + kd) = s4;
            }
            __syncthreads();
            const int kr = j0 + w * 8;     // global key base
            const int lk = w * 8;          // local in bufc
            unsigned a[4];
            a[0] = f2tf(scores[g * SROW + kr + tg]);
            a[1] = f2tf(scores[(g + 8) * SROW + kr + tg]);
            a[2] = f2tf(scores[g * SROW + kr + 4 + tg]);
            a[3] = f2tf(scores[(g + 8) * SROW + kr + 4 + tg]);
#pragma unroll
            for (int nt = 0; nt < 8; nt++) {
                unsigned bb[2];
                bb[0] = __float_as_uint(bufc[(lk + tg) * 68 + nt * 8 + g]);
                bb[1] = __float_as_uint(bufc[(lk + 4 + tg) * 68 + nt * 8 + g]);
                mma_tf32(pc[nt], a, bb);
            }
        }
        __syncthreads();   // all MMA reads done before partials alias the V buffers

#pragma unroll
        for (int nt = 0; nt < 8; nt++) {
            const int col = nt * 8 + tg * 2;
            *(float2*)&part[w * 1088 + g * 68 + col]       = make_float2(pc[nt][0], pc[nt][1]);
            *(float2*)&part[w * 1088 + (g + 8) * 68 + col] = make_float2(pc[nt][2], pc[nt][3]);
        }
        __syncthreads();
        for (int idx = t; idx < 1024; idx += 512) {
            const int i = idx >> 6, dd = idx & 63;
            float s = 0.0f;
#pragma unroll
            for (int ww = 0; ww < 16; ww++) s += part[ww * 1088 + i * 68 + dd];
            g_ao[((size_t)b * NS + q0 + i) * ND + h * HD + dd] = s * inv_s[i];
        }
    }
}

// ---------------- residual + LayerNorm, one block per (b,s) row --------------------
__global__ __launch_bounds__(256) void ln_kernel(const float* __restrict__ resid,
                                                 const float* __restrict__ gam,
                                                 const float* __restrict__ bet,
                                                 float* __restrict__ out)
{
    __shared__ float xb[ND];
    __shared__ float red[8];
    const int r = blockIdx.x;
    const int t = threadIdx.x;
    const int lane = t & 31, w = t >> 5;
    const size_t base = (size_t)r * ND;

    float lsum = 0.0f;
    for (int j = t; j < ND; j += 256) {
        const float x = g_ao[base + j] + resid[base + j];
        xb[j] = x;
        lsum += x;
    }
#pragma unroll
    for (int o = 16; o > 0; o >>= 1) lsum += __shfl_xor_sync(0xffffffffu, lsum, o);
    if (lane == 0) red[w] = lsum;
    __syncthreads();
    float tot = 0.0f;
#pragma unroll
    for (int w2 = 0; w2 < 8; w2++) tot += red[w2];
    const float mu = tot * (1.0f / ND);
    __syncthreads();

    float lv = 0.0f;
    for (int j = t; j < ND; j += 256) {
        const float dd = xb[j] - mu;
        lv += dd * dd;
    }
#pragma unroll
    for (int o = 16; o > 0; o >>= 1) lv += __shfl_xor_sync(0xffffffffu, lv, o);
    if (lane == 0) red[w] = lv;
    __syncthreads();
    float vtot = 0.0f;
#pragma unroll
    for (int w2 = 0; w2 < 8; w2++) vtot += red[w2];
    const float rstd = rsqrtf(vtot * (1.0f / ND) + 1e-5f);

    for (int j = t; j < ND; j += 256)
        out[base + j] = (xb[j] - mu) * rstd * gam[j] + bet[j];
}

// ---------------- launch -----------------------------------------------------------
extern "C" void kernel_launch(void* const* d_in, const int* in_sizes, int n_in,
                              void* d_out, int out_size)
{
    const float* q    = (const float*)d_in[0];
    const float* k    = (const float*)d_in[1];
    const float* v    = (const float*)d_in[2];
    const int*   mask = (const int*)  d_in[3];
    const float* Wq   = (const float*)d_in[4];
    const float* bq   = (const float*)d_in[5];
    const float* Wk   = (const float*)d_in[6];
    const float* bk   = (const float*)d_in[7];
    const float* Wv   = (const float*)d_in[8];
    const float* bv   = (const float*)d_in[9];
    const float* ln_g = (const float*)d_in[10];
    const float* ln_b = (const float*)d_in[11];
    float* out = (float*)d_out;

    cudaFuncSetAttribute(attn_kernel, cudaFuncAttributeMaxDynamicSharedMemorySize, SMEM_B);

    dim3 pg(64, 8);
    proj_kernel<<<pg, 256>>>(q, Wq, bq, 0);
    proj_kernel<<<pg, 256>>>(k, Wk, bk, 1);
    proj_kernel<<<pg, 256>>>(v, Wv, bv, 2);

    float* attn = nullptr;
    const long long need = (long long)NB * NS * ND + (long long)NB * NH * NS * NS;
    if ((long long)out_size >= need) attn = out + (size_t)NB * NS * ND;

    attn_kernel<<<NB * NH * (NS / 16), 512, SMEM_B>>>(mask, attn);
    ln_kernel<<<NB * NS, 256>>>(q, ln_g, ln_b, out);
}